// round 3
// baseline (speedup 1.0000x reference)
#include <cuda_runtime.h>
#include <cuda_bf16.h>
#include <cstdio>

// Problem constants
#define BSZ     4
#define SEQ     1024
#define DMODEL  2048
#define NHEADS  32
#define NKV     8
#define HDIM    64
#define KVDIM   512           // NKV * HDIM
#define GRP     4             // NHEADS / NKV
#define MROWS   (BSZ * SEQ)   // 4096

// Scratch (device globals: allowed; no cudaMalloc)
__device__ float g_q[MROWS * DMODEL];   // 32 MB
__device__ float g_k[MROWS * KVDIM];    //  8 MB
__device__ float g_v[MROWS * KVDIM];    //  8 MB
__device__ float g_ctx[MROWS * DMODEL]; // 32 MB

// ---------------------------------------------------------------------------
// Classic register-tiled SGEMM:  C[M,N] = A[M,K] @ W[K,N] + bias[N]
// BM=BN=128, BK=16, TM=TN=8, 256 threads. M%128==0, N%128==0, K%16==0 assumed.
// ---------------------------------------------------------------------------
#define GBM 128
#define GBN 128
#define GBK 16

__global__ __launch_bounds__(256) void sgemm_bias_kernel(
    const float* __restrict__ A, const float* __restrict__ W,
    const float* __restrict__ bias, float* __restrict__ C,
    int M, int N, int K)
{
    __shared__ float As[GBK][GBM];   // A tile stored transposed
    __shared__ float Bs[GBK][GBN];

    const int tid = threadIdx.x;
    const int tx = tid & 15;         // 0..15
    const int ty = tid >> 4;         // 0..15
    const int bm = blockIdx.y * GBM;
    const int bn = blockIdx.x * GBN;

    // A-tile load mapping: 128 rows x 16 cols = 512 float4; 2 per thread
    const int arow = tid >> 2;            // 0..63 (+64)
    const int acol = (tid & 3) << 2;      // 0,4,8,12
    // B-tile: 16 rows x 128 cols = 512 float4; 2 per thread
    const int brow = tid >> 5;            // 0..7 (+8)
    const int bcol = (tid & 31) << 2;     // 0..124

    float acc[8][8];
#pragma unroll
    for (int i = 0; i < 8; i++)
#pragma unroll
        for (int j = 0; j < 8; j++) acc[i][j] = 0.f;

    for (int k0 = 0; k0 < K; k0 += GBK) {
#pragma unroll
        for (int l = 0; l < 2; l++) {
            int r = arow + l * 64;
            float4 v = *(const float4*)&A[(size_t)(bm + r) * K + k0 + acol];
            As[acol + 0][r] = v.x;
            As[acol + 1][r] = v.y;
            As[acol + 2][r] = v.z;
            As[acol + 3][r] = v.w;
        }
#pragma unroll
        for (int l = 0; l < 2; l++) {
            int r = brow + l * 8;
            *(float4*)&Bs[r][bcol] =
                *(const float4*)&W[(size_t)(k0 + r) * N + bn + bcol];
        }
        __syncthreads();

#pragma unroll
        for (int k = 0; k < GBK; k++) {
            float a[8], b[8];
#pragma unroll
            for (int i = 0; i < 8; i++) a[i] = As[k][ty * 8 + i];
#pragma unroll
            for (int j = 0; j < 8; j++) b[j] = Bs[k][tx * 8 + j];
#pragma unroll
            for (int i = 0; i < 8; i++)
#pragma unroll
                for (int j = 0; j < 8; j++)
                    acc[i][j] = fmaf(a[i], b[j], acc[i][j]);
        }
        __syncthreads();
    }

    // Epilogue with bias
#pragma unroll
    for (int i = 0; i < 8; i++) {
        int row = bm + ty * 8 + i;
#pragma unroll
        for (int j4 = 0; j4 < 8; j4 += 4) {
            int col = bn + tx * 8 + j4;
            float4 o;
            o.x = acc[i][j4 + 0] + bias[col + 0];
            o.y = acc[i][j4 + 1] + bias[col + 1];
            o.z = acc[i][j4 + 2] + bias[col + 2];
            o.w = acc[i][j4 + 3] + bias[col + 3];
            *(float4*)&C[(size_t)row * N + col] = o;
        }
    }
}

// ---------------------------------------------------------------------------
// Flash attention (fp32, online softmax).
// Grid: (SEQ/128, BSZ*NHEADS). Block: 256 threads.
// Per CTA: 128 query rows of one (b,h); loop over 8 key blocks of 128.
// Thread (ty,tx) of 16x16: owns S rows ty*8..+7, S cols tx*8..+7,
// and ctx rows ty*8..+7 x cols tx*4..+3.
// ---------------------------------------------------------------------------
#define FBM 128
#define FBN 128
#define QPAD 68     // 64+4, keeps float4 alignment
#define PPAD 132    // 128+4

// shared floats: 3 * 128*68 + 128*132
#define FLASH_SMEM_FLOATS (3 * FBM * QPAD + FBM * PPAD)
#define FLASH_SMEM_BYTES  (FLASH_SMEM_FLOATS * 4)

__global__ __launch_bounds__(256) void flash_attn_kernel()
{
    extern __shared__ float smem[];
    float (*sQ)[QPAD] = (float(*)[QPAD])smem;
    float (*sK)[QPAD] = (float(*)[QPAD])(smem + FBM * QPAD);
    float (*sV)[QPAD] = (float(*)[QPAD])(smem + 2 * FBM * QPAD);
    float (*sP)[PPAD] = (float(*)[PPAD])(smem + 3 * FBM * QPAD);

    const int tid = threadIdx.x;
    const int tx = tid & 15;
    const int ty = tid >> 4;

    const int bh = blockIdx.y;
    const int b  = bh >> 5;          // / NHEADS
    const int h  = bh & 31;
    const int kvh = h >> 2;          // h / GRP
    const int q0 = blockIdx.x * FBM;

    const float* Qp = g_q + ((size_t)(b * SEQ + q0)) * DMODEL + h * HDIM;
    const float* Kp = g_k + (size_t)b * SEQ * KVDIM + kvh * HDIM;
    const float* Vp = g_v + (size_t)b * SEQ * KVDIM + kvh * HDIM;

    // Load Q tile: 128 rows x 64 floats = 2048 float4, 8 per thread
#pragma unroll
    for (int l = 0; l < 8; l++) {
        int e = tid + l * 256;
        int r = e >> 4;
        int d4 = (e & 15) << 2;
        *(float4*)&sQ[r][d4] = *(const float4*)&Qp[(size_t)r * DMODEL + d4];
    }

    float acc[8][4];
    float m_i[8], l_i[8];
#pragma unroll
    for (int i = 0; i < 8; i++) {
        m_i[i] = -1e30f;
        l_i[i] = 0.f;
#pragma unroll
        for (int c = 0; c < 4; c++) acc[i][c] = 0.f;
    }

    for (int kb = 0; kb < SEQ / FBN; kb++) {
        __syncthreads();   // protect sK/sV/sP from previous iteration readers
        // Load K,V blocks
#pragma unroll
        for (int l = 0; l < 8; l++) {
            int e = tid + l * 256;
            int r = e >> 4;
            int d4 = (e & 15) << 2;
            size_t goff = (size_t)(kb * FBN + r) * KVDIM + d4;
            *(float4*)&sK[r][d4] = *(const float4*)&Kp[goff];
            *(float4*)&sV[r][d4] = *(const float4*)&Vp[goff];
        }
        __syncthreads();

        // S = (Q @ K^T) * 1/sqrt(64)
        float s[8][8];
#pragma unroll
        for (int i = 0; i < 8; i++)
#pragma unroll
            for (int j = 0; j < 8; j++) s[i][j] = 0.f;

#pragma unroll 16
        for (int d = 0; d < HDIM; d++) {
            float a[8], bb[8];
#pragma unroll
            for (int i = 0; i < 8; i++) a[i] = sQ[ty * 8 + i][d];
#pragma unroll
            for (int j = 0; j < 8; j++) bb[j] = sK[tx * 8 + j][d];
#pragma unroll
            for (int i = 0; i < 8; i++)
#pragma unroll
                for (int j = 0; j < 8; j++)
                    s[i][j] = fmaf(a[i], bb[j], s[i][j]);
        }

        // Online softmax per row
#pragma unroll
        for (int i = 0; i < 8; i++) {
            float mx = s[i][0];
#pragma unroll
            for (int j = 1; j < 8; j++) mx = fmaxf(mx, s[i][j]);
            mx *= 0.125f;
            // reduce max across the 16 tx lanes (xor <16 stays in half-warp = same ty)
#pragma unroll
            for (int off = 8; off >= 1; off >>= 1)
                mx = fmaxf(mx, __shfl_xor_sync(0xffffffffu, mx, off));

            float m_new = fmaxf(m_i[i], mx);
            float corr = __expf(m_i[i] - m_new);
            m_i[i] = m_new;

            float rs = 0.f;
#pragma unroll
            for (int j = 0; j < 8; j++) {
                float p = __expf(s[i][j] * 0.125f - m_new);
                sP[ty * 8 + i][tx * 8 + j] = p;
                rs += p;
            }
#pragma unroll
            for (int off = 8; off >= 1; off >>= 1)
                rs += __shfl_xor_sync(0xffffffffu, rs, off);

            l_i[i] = l_i[i] * corr + rs;
#pragma unroll
            for (int c = 0; c < 4; c++) acc[i][c] *= corr;
        }
        __syncthreads();   // sP fully written before PV

        // acc += P @ V
#pragma unroll 8
        for (int j = 0; j < FBN; j++) {
            float4 bv = *(const float4*)&sV[j][tx * 4];
            float ap[8];
#pragma unroll
            for (int i = 0; i < 8; i++) ap[i] = sP[ty * 8 + i][j];
#pragma unroll
            for (int i = 0; i < 8; i++) {
                acc[i][0] = fmaf(ap[i], bv.x, acc[i][0]);
                acc[i][1] = fmaf(ap[i], bv.y, acc[i][1]);
                acc[i][2] = fmaf(ap[i], bv.z, acc[i][2]);
                acc[i][3] = fmaf(ap[i], bv.w, acc[i][3]);
            }
        }
    }

    // Normalize and write ctx
#pragma unroll
    for (int i = 0; i < 8; i++) {
        float inv = 1.f / l_i[i];
        int row = q0 + ty * 8 + i;
        float4 o;
        o.x = acc[i][0] * inv;
        o.y = acc[i][1] * inv;
        o.z = acc[i][2] * inv;
        o.w = acc[i][3] * inv;
        *(float4*)&g_ctx[((size_t)(b * SEQ + row)) * DMODEL + h * HDIM + tx * 4] = o;
    }
}

// ---------------------------------------------------------------------------
extern "C" void kernel_launch(void* const* d_in, const int* in_sizes, int n_in,
                              void* d_out, int out_size)
{
    const float* x  = (const float*)d_in[0];
    const float* Wq = (const float*)d_in[1];
    const float* bq = (const float*)d_in[2];
    const float* Wk = (const float*)d_in[3];
    const float* bk = (const float*)d_in[4];
    const float* Wv = (const float*)d_in[5];
    const float* bv = (const float*)d_in[6];
    const float* Wo = (const float*)d_in[7];
    const float* bo = (const float*)d_in[8];
    float* out = (float*)d_out;

    float *pq, *pk, *pv, *pctx;
    cudaGetSymbolAddress((void**)&pq,   g_q);
    cudaGetSymbolAddress((void**)&pk,   g_k);
    cudaGetSymbolAddress((void**)&pv,   g_v);
    cudaGetSymbolAddress((void**)&pctx, g_ctx);

    cudaFuncSetAttribute(flash_attn_kernel,
                         cudaFuncAttributeMaxDynamicSharedMemorySize,
                         FLASH_SMEM_BYTES);

    dim3 blk(256);
    // QKV projections
    sgemm_bias_kernel<<<dim3(DMODEL / GBN, MROWS / GBM), blk>>>(
        x, Wq, bq, pq, MROWS, DMODEL, DMODEL);
    sgemm_bias_kernel<<<dim3(KVDIM / GBN, MROWS / GBM), blk>>>(
        x, Wk, bk, pk, MROWS, KVDIM, DMODEL);
    sgemm_bias_kernel<<<dim3(KVDIM / GBN, MROWS / GBM), blk>>>(
        x, Wv, bv, pv, MROWS, KVDIM, DMODEL);

    // Fused attention
    flash_attn_kernel<<<dim3(SEQ / FBM, BSZ * NHEADS), blk, FLASH_SMEM_BYTES>>>();

    // Output projection directly into d_out
    sgemm_bias_kernel<<<dim3(DMODEL / GBN, MROWS / GBM), blk>>>(
        pctx, Wo, bo, out, MROWS, DMODEL, DMODEL);
}

// round 5
// speedup vs baseline: 3.0184x; 3.0184x over previous
#include <cuda_runtime.h>
#include <cuda_bf16.h>
#include <cstdint>

#define BSZ 4
#define SEQ 1024
#define DMODEL 2048
#define NHEADS 32
#define NKV 8
#define HDIM 64
#define KVDIM 512
#define MROWS (BSZ*SEQ)

// ---------------------------------------------------------------------------
// bf16 hi/lo split scratch (device globals: no allocation)
// ---------------------------------------------------------------------------
__device__ __nv_bfloat16 g_xh[MROWS*DMODEL], g_xl[MROWS*DMODEL];
__device__ __nv_bfloat16 g_qh[MROWS*DMODEL], g_ql[MROWS*DMODEL];
__device__ __nv_bfloat16 g_kh[MROWS*KVDIM],  g_kl[MROWS*KVDIM];
__device__ __nv_bfloat16 g_vh[MROWS*KVDIM],  g_vl[MROWS*KVDIM];
__device__ __nv_bfloat16 g_ch[MROWS*DMODEL], g_cl[MROWS*DMODEL];
__device__ __nv_bfloat16 g_wqh[DMODEL*DMODEL], g_wql[DMODEL*DMODEL];
__device__ __nv_bfloat16 g_wkh[DMODEL*KVDIM],  g_wkl[DMODEL*KVDIM];
__device__ __nv_bfloat16 g_wvh[DMODEL*KVDIM],  g_wvl[DMODEL*KVDIM];
__device__ __nv_bfloat16 g_woh[DMODEL*DMODEL], g_wol[DMODEL*DMODEL];

// ---------------------------------------------------------------------------
// PTX helpers
// ---------------------------------------------------------------------------
__device__ __forceinline__ uint32_t smem_u32(const void* p) {
    return (uint32_t)__cvta_generic_to_shared(p);
}
__device__ __forceinline__ void ldx4(uint32_t r[4], uint32_t addr) {
    asm volatile("ldmatrix.sync.aligned.m8n8.x4.shared.b16 {%0,%1,%2,%3}, [%4];"
                 : "=r"(r[0]), "=r"(r[1]), "=r"(r[2]), "=r"(r[3]) : "r"(addr));
}
__device__ __forceinline__ void ldx4t(uint32_t r[4], uint32_t addr) {
    asm volatile("ldmatrix.sync.aligned.m8n8.x4.trans.shared.b16 {%0,%1,%2,%3}, [%4];"
                 : "=r"(r[0]), "=r"(r[1]), "=r"(r[2]), "=r"(r[3]) : "r"(addr));
}
__device__ __forceinline__ void mma16816(float c[4], const uint32_t a[4], const uint32_t b[2]) {
    asm volatile("mma.sync.aligned.m16n8k16.row.col.f32.bf16.bf16.f32 "
                 "{%0,%1,%2,%3}, {%4,%5,%6,%7}, {%8,%9}, {%0,%1,%2,%3};"
                 : "+f"(c[0]), "+f"(c[1]), "+f"(c[2]), "+f"(c[3])
                 : "r"(a[0]), "r"(a[1]), "r"(a[2]), "r"(a[3]), "r"(b[0]), "r"(b[1]));
}
__device__ __forceinline__ void cp16(void* dst, const void* src) {
    uint32_t d = smem_u32(dst);
    asm volatile("cp.async.cg.shared.global [%0], [%1], 16;" :: "r"(d), "l"(src));
}
#define CP_COMMIT() asm volatile("cp.async.commit_group;")
#define CP_WAIT0()  asm volatile("cp.async.wait_group 0;")
#define CP_WAIT1()  asm volatile("cp.async.wait_group 1;")
__device__ __forceinline__ float ex2(float x) {
    float r; asm("ex2.approx.f32 %0, %1;" : "=f"(r) : "f"(x)); return r;
}

// ---------------------------------------------------------------------------
// fp32 -> (bf16 hi, bf16 lo) split, vectorized x4
// ---------------------------------------------------------------------------
__global__ void split_kernel(const float4* __restrict__ in,
                             __nv_bfloat162* __restrict__ hi,
                             __nv_bfloat162* __restrict__ lo, int n4)
{
    int i = blockIdx.x * blockDim.x + threadIdx.x;
    if (i >= n4) return;
    float4 f = in[i];
    __nv_bfloat16 h0 = __float2bfloat16(f.x), h1 = __float2bfloat16(f.y);
    __nv_bfloat16 h2 = __float2bfloat16(f.z), h3 = __float2bfloat16(f.w);
    hi[2*i]   = __halves2bfloat162(h0, h1);
    hi[2*i+1] = __halves2bfloat162(h2, h3);
    lo[2*i]   = __floats2bfloat162_rn(f.x - __bfloat162float(h0), f.y - __bfloat162float(h1));
    lo[2*i+1] = __floats2bfloat162_rn(f.z - __bfloat162float(h2), f.w - __bfloat162float(h3));
}

// ---------------------------------------------------------------------------
// Split-bf16 MMA GEMM: C[M,N] = A@B + bias with A = Ah+Al, B = Bh+Bl
// C = Ah*Bh + Ah*Bl + Al*Bh (3 mma per tile). Block 128x128, BK=16, 8 warps
// (warp tile 64x32). cp.async double-buffered. Output fp32 (Cf) or hi/lo bf16.
// ---------------------------------------------------------------------------
#define APAD 24    // 16 + 8 pad (48B rows: conflict-free ldmatrix)
#define BPAD 136   // 128 + 8 pad (272B rows)

__global__ __launch_bounds__(256) void mma_gemm(
    const __nv_bfloat16* __restrict__ Ahg, const __nv_bfloat16* __restrict__ Alg,
    const __nv_bfloat16* __restrict__ Bhg, const __nv_bfloat16* __restrict__ Blg,
    const float* __restrict__ bias,
    __nv_bfloat16* __restrict__ Ch, __nv_bfloat16* __restrict__ Cl,
    float* __restrict__ Cf,
    int M, int N, int K)
{
    __shared__ __align__(16) __nv_bfloat16 sAh[2][128][APAD];
    __shared__ __align__(16) __nv_bfloat16 sAl[2][128][APAD];
    __shared__ __align__(16) __nv_bfloat16 sBh[2][16][BPAD];
    __shared__ __align__(16) __nv_bfloat16 sBl[2][16][BPAD];

    const int tid  = threadIdx.x;
    const int lane = tid & 31;
    const int warp = tid >> 5;
    const int wm = (warp & 1) * 64;    // warp grid 2(M) x 4(N)
    const int wn = (warp >> 1) * 32;
    const int bm = blockIdx.y * 128;
    const int bn = blockIdx.x * 128;

    // cp.async load mapping
    const int ar = tid >> 1, ac = (tid & 1) * 8;       // A: 128 rows x 16
    const int br = tid >> 4, bc = (tid & 15) * 8;      // B: 16 rows x 128

    // ldmatrix lane addressing
    const int a_row = lane & 15;                 // + tile base
    const int a_col = (lane >> 4) * 8;
    const int b_row = ((lane >> 3) & 1) * 8 + (lane & 7);
    const int b_col = (lane >> 4) * 8;           // + wn + np*16

    float acc[4][4][4];
#pragma unroll
    for (int i = 0; i < 4; i++)
#pragma unroll
        for (int j = 0; j < 4; j++)
#pragma unroll
            for (int v = 0; v < 4; v++) acc[i][j][v] = 0.f;

    const int NS = K >> 4;

    // prologue: stage 0
    cp16(&sAh[0][ar][ac], Ahg + (size_t)(bm + ar) * K + ac);
    cp16(&sAl[0][ar][ac], Alg + (size_t)(bm + ar) * K + ac);
    cp16(&sBh[0][br][bc], Bhg + (size_t)br * N + bn + bc);
    cp16(&sBl[0][br][bc], Blg + (size_t)br * N + bn + bc);
    CP_COMMIT();

#pragma unroll 1
    for (int s = 0; s < NS; ++s) {
        const int buf = s & 1;
        if (s + 1 < NS) {
            const int k0 = (s + 1) << 4;
            const int nb = buf ^ 1;
            cp16(&sAh[nb][ar][ac], Ahg + (size_t)(bm + ar) * K + k0 + ac);
            cp16(&sAl[nb][ar][ac], Alg + (size_t)(bm + ar) * K + k0 + ac);
            cp16(&sBh[nb][br][bc], Bhg + (size_t)(k0 + br) * N + bn + bc);
            cp16(&sBl[nb][br][bc], Blg + (size_t)(k0 + br) * N + bn + bc);
            CP_COMMIT(); CP_WAIT1();
        } else {
            CP_WAIT0();
        }
        __syncthreads();

        uint32_t ah[4][4], al[4][4];
#pragma unroll
        for (int mt = 0; mt < 4; mt++) {
            ldx4(ah[mt], smem_u32(&sAh[buf][wm + mt * 16 + a_row][a_col]));
            ldx4(al[mt], smem_u32(&sAl[buf][wm + mt * 16 + a_row][a_col]));
        }
        uint32_t bh[4][2], bl[4][2];
#pragma unroll
        for (int np = 0; np < 2; np++) {
            uint32_t r[4];
            ldx4t(r, smem_u32(&sBh[buf][b_row][wn + np * 16 + b_col]));
            bh[np*2][0] = r[0]; bh[np*2][1] = r[1];
            bh[np*2+1][0] = r[2]; bh[np*2+1][1] = r[3];
            ldx4t(r, smem_u32(&sBl[buf][b_row][wn + np * 16 + b_col]));
            bl[np*2][0] = r[0]; bl[np*2][1] = r[1];
            bl[np*2+1][0] = r[2]; bl[np*2+1][1] = r[3];
        }
#pragma unroll
        for (int mt = 0; mt < 4; mt++)
#pragma unroll
            for (int nt = 0; nt < 4; nt++) {
                mma16816(acc[mt][nt], ah[mt], bh[nt]);
                mma16816(acc[mt][nt], ah[mt], bl[nt]);
                mma16816(acc[mt][nt], al[mt], bh[nt]);
            }
        __syncthreads();
    }

    // epilogue
    const int er = lane >> 2;
    const int ec = (lane & 3) * 2;
#pragma unroll
    for (int mt = 0; mt < 4; mt++) {
#pragma unroll
        for (int nt = 0; nt < 4; nt++) {
            int row = bm + wm + mt * 16 + er;
            int col = bn + wn + nt * 8 + ec;
            float b0 = bias[col], b1 = bias[col + 1];
            float v00 = acc[mt][nt][0] + b0, v01 = acc[mt][nt][1] + b1;
            float v10 = acc[mt][nt][2] + b0, v11 = acc[mt][nt][3] + b1;
            if (Cf) {
                *(float2*)&Cf[(size_t)row * N + col]       = make_float2(v00, v01);
                *(float2*)&Cf[(size_t)(row + 8) * N + col] = make_float2(v10, v11);
            } else {
                __nv_bfloat16 h00 = __float2bfloat16(v00), h01 = __float2bfloat16(v01);
                __nv_bfloat16 h10 = __float2bfloat16(v10), h11 = __float2bfloat16(v11);
                *(__nv_bfloat162*)&Ch[(size_t)row * N + col] = __halves2bfloat162(h00, h01);
                *(__nv_bfloat162*)&Cl[(size_t)row * N + col] =
                    __floats2bfloat162_rn(v00 - __bfloat162float(h00), v01 - __bfloat162float(h01));
                *(__nv_bfloat162*)&Ch[(size_t)(row + 8) * N + col] = __halves2bfloat162(h10, h11);
                *(__nv_bfloat162*)&Cl[(size_t)(row + 8) * N + col] =
                    __floats2bfloat162_rn(v10 - __bfloat162float(h10), v11 - __bfloat162float(h11));
            }
        }
    }
}

// ---------------------------------------------------------------------------
// Flash attention on MMA (split bf16). Grid (SEQ/128, BSZ*NHEADS), 256 thr.
// 8 warps x 16 query rows each; per kb: S = QK^T (K=64), online softmax,
// ctx += P@V (K=128). S accumulator fragments reused directly as P A-frags.
// ---------------------------------------------------------------------------
#define FQP 72   // 64 + 8 pad (144B rows)
#define FLASH_SMEM (4 * 128 * FQP * 2)   // Kh,Kl,Vh,Vl

__global__ __launch_bounds__(256) void flash_mma_kernel()
{
    extern __shared__ __align__(16) __nv_bfloat16 fsm[];
    __nv_bfloat16 (*sKh)[FQP] = (__nv_bfloat16(*)[FQP])(fsm);
    __nv_bfloat16 (*sKl)[FQP] = (__nv_bfloat16(*)[FQP])(fsm + 128 * FQP);
    __nv_bfloat16 (*sVh)[FQP] = (__nv_bfloat16(*)[FQP])(fsm + 2 * 128 * FQP);
    __nv_bfloat16 (*sVl)[FQP] = (__nv_bfloat16(*)[FQP])(fsm + 3 * 128 * FQP);

    const int tid  = threadIdx.x;
    const int lane = tid & 31;
    const int warp = tid >> 5;

    const int bhid = blockIdx.y;
    const int b    = bhid >> 5;
    const int h    = bhid & 31;
    const int kvh  = h >> 2;
    const int q0   = blockIdx.x * 128;

    const __nv_bfloat16* Qh_g = g_qh + (size_t)(b * SEQ + q0) * DMODEL + h * HDIM;
    const __nv_bfloat16* Ql_g = g_ql + (size_t)(b * SEQ + q0) * DMODEL + h * HDIM;
    const __nv_bfloat16* Kh_g = g_kh + (size_t)(b * SEQ) * KVDIM + kvh * HDIM;
    const __nv_bfloat16* Kl_g = g_kl + (size_t)(b * SEQ) * KVDIM + kvh * HDIM;
    const __nv_bfloat16* Vh_g = g_vh + (size_t)(b * SEQ) * KVDIM + kvh * HDIM;
    const __nv_bfloat16* Vl_g = g_vl + (size_t)(b * SEQ) * KVDIM + kvh * HDIM;

    // ---- stage Q into K region, extract fragments, then free the region ----
#pragma unroll
    for (int l = 0; l < 4; l++) {
        int id = tid + l * 256;        // 0..1023
        int row = id >> 3, c = (id & 7) * 8;
        cp16(&sKh[row][c], Qh_g + (size_t)row * DMODEL + c);
        cp16(&sKl[row][c], Ql_g + (size_t)row * DMODEL + c);
    }
    CP_COMMIT(); CP_WAIT0();
    __syncthreads();

    const int a_row = lane & 15;
    const int a_col = (lane >> 4) * 8;
    uint32_t qh[4][4], ql[4][4];
#pragma unroll
    for (int ks = 0; ks < 4; ks++) {
        ldx4(qh[ks], smem_u32(&sKh[warp * 16 + a_row][ks * 16 + a_col]));
        ldx4(ql[ks], smem_u32(&sKl[warp * 16 + a_row][ks * 16 + a_col]));
    }

    float s[16][4];
    float o[8][4];
#pragma unroll
    for (int i = 0; i < 8; i++)
#pragma unroll
        for (int j = 0; j < 4; j++) o[i][j] = 0.f;
    float m0 = -1e30f, m1 = -1e30f, sum0 = 0.f, sum1 = 0.f;

    const int t_row = ((lane >> 3) & 1) * 8 + (lane & 7);   // trans-ldmatrix row
    const int t_col = (lane >> 4) * 8;

#pragma unroll 1
    for (int kb = 0; kb < SEQ / 128; kb++) {
        __syncthreads();   // Q frags done (kb=0) / prior iter smem reads done
#pragma unroll
        for (int l = 0; l < 4; l++) {
            int id = tid + l * 256;
            int row = id >> 3, c = (id & 7) * 8;
            size_t go = (size_t)(kb * 128 + row) * KVDIM + c;
            cp16(&sKh[row][c], Kh_g + go);
            cp16(&sKl[row][c], Kl_g + go);
            cp16(&sVh[row][c], Vh_g + go);
            cp16(&sVl[row][c], Vl_g + go);
        }
        CP_COMMIT(); CP_WAIT0();
        __syncthreads();

        // ---- S = Q @ K^T ----
#pragma unroll
        for (int i = 0; i < 16; i++)
#pragma unroll
            for (int j = 0; j < 4; j++) s[i][j] = 0.f;

#pragma unroll
        for (int ntp = 0; ntp < 8; ntp++) {
#pragma unroll
            for (int ks = 0; ks < 4; ks++) {
                uint32_t rh[4], rl[4];
                ldx4(rh, smem_u32(&sKh[ntp * 16 + a_row][ks * 16 + a_col]));
                ldx4(rl, smem_u32(&sKl[ntp * 16 + a_row][ks * 16 + a_col]));
                uint32_t b0h[2] = {rh[0], rh[2]}, b1h[2] = {rh[1], rh[3]};
                uint32_t b0l[2] = {rl[0], rl[2]}, b1l[2] = {rl[1], rl[3]};
                mma16816(s[2*ntp],   qh[ks], b0h);
                mma16816(s[2*ntp],   qh[ks], b0l);
                mma16816(s[2*ntp],   ql[ks], b0h);
                mma16816(s[2*ntp+1], qh[ks], b1h);
                mma16816(s[2*ntp+1], qh[ks], b1l);
                mma16816(s[2*ntp+1], ql[ks], b1h);
            }
        }

        // ---- online softmax (base-2 domain) ----
        const float C2 = 0.18033688011112042f;   // log2(e)/sqrt(64)
        float mx0 = -1e30f, mx1 = -1e30f;
#pragma unroll
        for (int i = 0; i < 16; i++) {
            s[i][0] *= C2; s[i][1] *= C2; s[i][2] *= C2; s[i][3] *= C2;
            mx0 = fmaxf(mx0, fmaxf(s[i][0], s[i][1]));
            mx1 = fmaxf(mx1, fmaxf(s[i][2], s[i][3]));
        }
        mx0 = fmaxf(mx0, __shfl_xor_sync(0xffffffffu, mx0, 1));
        mx0 = fmaxf(mx0, __shfl_xor_sync(0xffffffffu, mx0, 2));
        mx1 = fmaxf(mx1, __shfl_xor_sync(0xffffffffu, mx1, 1));
        mx1 = fmaxf(mx1, __shfl_xor_sync(0xffffffffu, mx1, 2));

        float nm0 = fmaxf(m0, mx0), nm1 = fmaxf(m1, mx1);
        float c0 = ex2(m0 - nm0), c1 = ex2(m1 - nm1);
        m0 = nm0; m1 = nm1;

        float rs0 = 0.f, rs1 = 0.f;
#pragma unroll
        for (int i = 0; i < 16; i++) {
            s[i][0] = ex2(s[i][0] - nm0); rs0 += s[i][0];
            s[i][1] = ex2(s[i][1] - nm0); rs0 += s[i][1];
            s[i][2] = ex2(s[i][2] - nm1); rs1 += s[i][2];
            s[i][3] = ex2(s[i][3] - nm1); rs1 += s[i][3];
        }
        rs0 += __shfl_xor_sync(0xffffffffu, rs0, 1);
        rs0 += __shfl_xor_sync(0xffffffffu, rs0, 2);
        rs1 += __shfl_xor_sync(0xffffffffu, rs1, 1);
        rs1 += __shfl_xor_sync(0xffffffffu, rs1, 2);
        sum0 = sum0 * c0 + rs0;
        sum1 = sum1 * c1 + rs1;
#pragma unroll
        for (int nt = 0; nt < 8; nt++) {
            o[nt][0] *= c0; o[nt][1] *= c0;
            o[nt][2] *= c1; o[nt][3] *= c1;
        }

        // ---- ctx += P @ V ----
#pragma unroll
        for (int ks = 0; ks < 8; ks++) {
            // P A-frags for keys ks*16..+15 = S tiles 2ks, 2ks+1
            float p00 = s[2*ks][0],   p01 = s[2*ks][1],   p10 = s[2*ks][2],   p11 = s[2*ks][3];
            float r00 = s[2*ks+1][0], r01 = s[2*ks+1][1], r10 = s[2*ks+1][2], r11 = s[2*ks+1][3];
            __nv_bfloat16 hp00 = __float2bfloat16(p00), hp01 = __float2bfloat16(p01);
            __nv_bfloat16 hp10 = __float2bfloat16(p10), hp11 = __float2bfloat16(p11);
            __nv_bfloat16 hr00 = __float2bfloat16(r00), hr01 = __float2bfloat16(r01);
            __nv_bfloat16 hr10 = __float2bfloat16(r10), hr11 = __float2bfloat16(r11);
            __nv_bfloat162 t;
            uint32_t ph[4], pl[4];
            t = __halves2bfloat162(hp00, hp01); ph[0] = *(uint32_t*)&t;
            t = __halves2bfloat162(hp10, hp11); ph[1] = *(uint32_t*)&t;
            t = __halves2bfloat162(hr00, hr01); ph[2] = *(uint32_t*)&t;
            t = __halves2bfloat162(hr10, hr11); ph[3] = *(uint32_t*)&t;
            t = __floats2bfloat162_rn(p00 - __bfloat162float(hp00), p01 - __bfloat162float(hp01)); pl[0] = *(uint32_t*)&t;
            t = __floats2bfloat162_rn(p10 - __bfloat162float(hp10), p11 - __bfloat162float(hp11)); pl[1] = *(uint32_t*)&t;
            t = __floats2bfloat162_rn(r00 - __bfloat162float(hr00), r01 - __bfloat162float(hr01)); pl[2] = *(uint32_t*)&t;
            t = __floats2bfloat162_rn(r10 - __bfloat162float(hr10), r11 - __bfloat162float(hr11)); pl[3] = *(uint32_t*)&t;

#pragma unroll
            for (int np = 0; np < 4; np++) {
                uint32_t vh4[4], vl4[4];
                ldx4t(vh4, smem_u32(&sVh[ks * 16 + t_row][np * 16 + t_col]));
                ldx4t(vl4, smem_u32(&sVl[ks * 16 + t_row][np * 16 + t_col]));
                uint32_t v0h[2] = {vh4[0], vh4[1]}, v1h[2] = {vh4[2], vh4[3]};
                uint32_t v0l[2] = {vl4[0], vl4[1]}, v1l[2] = {vl4[2], vl4[3]};
                mma16816(o[np*2],   ph, v0h);
                mma16816(o[np*2],   ph, v0l);
                mma16816(o[np*2],   pl, v0h);
                mma16816(o[np*2+1], ph, v1h);
                mma16816(o[np*2+1], ph, v1l);
                mma16816(o[np*2+1], pl, v1h);
            }
        }
    }

    // ---- normalize + write ctx as hi/lo bf16 ----
    float inv0 = 1.f / sum0, inv1 = 1.f / sum1;
    int row0 = b * SEQ + q0 + warp * 16 + (lane >> 2);
    int colb = h * HDIM + (lane & 3) * 2;
#pragma unroll
    for (int nt = 0; nt < 8; nt++) {
        int col = colb + nt * 8;
        float v00 = o[nt][0] * inv0, v01 = o[nt][1] * inv0;
        float v10 = o[nt][2] * inv1, v11 = o[nt][3] * inv1;
        __nv_bfloat16 h00 = __float2bfloat16(v00), h01 = __float2bfloat16(v01);
        __nv_bfloat16 h10 = __float2bfloat16(v10), h11 = __float2bfloat16(v11);
        size_t o0 = (size_t)row0 * DMODEL + col;
        size_t o1 = (size_t)(row0 + 8) * DMODEL + col;
        *(__nv_bfloat162*)&g_ch[o0] = __halves2bfloat162(h00, h01);
        *(__nv_bfloat162*)&g_cl[o0] =
            __floats2bfloat162_rn(v00 - __bfloat162float(h00), v01 - __bfloat162float(h01));
        *(__nv_bfloat162*)&g_ch[o1] = __halves2bfloat162(h10, h11);
        *(__nv_bfloat162*)&g_cl[o1] =
            __floats2bfloat162_rn(v10 - __bfloat162float(h10), v11 - __bfloat162float(h11));
    }
}

// ---------------------------------------------------------------------------
extern "C" void kernel_launch(void* const* d_in, const int* in_sizes, int n_in,
                              void* d_out, int out_size)
{
    const float* x  = (const float*)d_in[0];
    const float* Wq = (const float*)d_in[1];
    const float* bq = (const float*)d_in[2];
    const float* Wk = (const float*)d_in[3];
    const float* bk = (const float*)d_in[4];
    const float* Wv = (const float*)d_in[5];
    const float* bv = (const float*)d_in[6];
    const float* Wo = (const float*)d_in[7];
    const float* bo = (const float*)d_in[8];
    float* out = (float*)d_out;

    __nv_bfloat16 *xh, *xl, *qh, *ql, *kh, *kl, *vh, *vl, *ch, *cl;
    __nv_bfloat16 *wqh, *wql, *wkh, *wkl, *wvh, *wvl, *woh, *wol;
    cudaGetSymbolAddress((void**)&xh, g_xh);   cudaGetSymbolAddress((void**)&xl, g_xl);
    cudaGetSymbolAddress((void**)&qh, g_qh);   cudaGetSymbolAddress((void**)&ql, g_ql);
    cudaGetSymbolAddress((void**)&kh, g_kh);   cudaGetSymbolAddress((void**)&kl, g_kl);
    cudaGetSymbolAddress((void**)&vh, g_vh);   cudaGetSymbolAddress((void**)&vl, g_vl);
    cudaGetSymbolAddress((void**)&ch, g_ch);   cudaGetSymbolAddress((void**)&cl, g_cl);
    cudaGetSymbolAddress((void**)&wqh, g_wqh); cudaGetSymbolAddress((void**)&wql, g_wql);
    cudaGetSymbolAddress((void**)&wkh, g_wkh); cudaGetSymbolAddress((void**)&wkl, g_wkl);
    cudaGetSymbolAddress((void**)&wvh, g_wvh); cudaGetSymbolAddress((void**)&wvl, g_wvl);
    cudaGetSymbolAddress((void**)&woh, g_woh); cudaGetSymbolAddress((void**)&wol, g_wol);

    cudaFuncSetAttribute(flash_mma_kernel,
                         cudaFuncAttributeMaxDynamicSharedMemorySize, FLASH_SMEM);

    auto nblk = [](int n4) { return (n4 + 255) / 256; };

    int nx  = MROWS * DMODEL / 4;
    int nwq = DMODEL * DMODEL / 4;
    int nwk = DMODEL * KVDIM / 4;
    split_kernel<<<nblk(nx), 256>>>((const float4*)x,  (__nv_bfloat162*)xh,  (__nv_bfloat162*)xl,  nx);
    split_kernel<<<nblk(nwq), 256>>>((const float4*)Wq, (__nv_bfloat162*)wqh, (__nv_bfloat162*)wql, nwq);
    split_kernel<<<nblk(nwk), 256>>>((const float4*)Wk, (__nv_bfloat162*)wkh, (__nv_bfloat162*)wkl, nwk);
    split_kernel<<<nblk(nwk), 256>>>((const float4*)Wv, (__nv_bfloat162*)wvh, (__nv_bfloat162*)wvl, nwk);
    split_kernel<<<nblk(nwq), 256>>>((const float4*)Wo, (__nv_bfloat162*)woh, (__nv_bfloat162*)wol, nwq);

    dim3 blk(256);
    dim3 gq(DMODEL / 128, MROWS / 128);
    dim3 gkv(KVDIM / 128, MROWS / 128);

    mma_gemm<<<gq,  blk>>>(xh, xl, wqh, wql, bq, qh, ql, nullptr, MROWS, DMODEL, DMODEL);
    mma_gemm<<<gkv, blk>>>(xh, xl, wkh, wkl, bk, kh, kl, nullptr, MROWS, KVDIM, DMODEL);
    mma_gemm<<<gkv, blk>>>(xh, xl, wvh, wvl, bv, vh, vl, nullptr, MROWS, KVDIM, DMODEL);

    flash_mma_kernel<<<dim3(SEQ / 128, BSZ * NHEADS), blk, FLASH_SMEM>>>();

    mma_gemm<<<gq, blk>>>(ch, cl, woh, wol, bo, nullptr, nullptr, out, MROWS, DMODEL, DMODEL);
}

// round 7
// speedup vs baseline: 3.2094x; 1.0633x over previous
#include <cuda_runtime.h>
#include <cuda_bf16.h>
#include <cstdint>

#define BSZ 4
#define SEQ 1024
#define DMODEL 2048
#define NHEADS 32
#define NKV 8
#define HDIM 64
#define KVDIM 512
#define MROWS (BSZ*SEQ)
#define QKVN 3072          // packed Q|K|V columns

// ---------------------------------------------------------------------------
// Scratch (device globals)
// ---------------------------------------------------------------------------
__device__ __nv_bfloat16 g_xh[MROWS*DMODEL],  g_xl[MROWS*DMODEL];
__device__ __nv_bfloat16 g_qkvh[MROWS*QKVN],  g_qkvl[MROWS*QKVN];
__device__ __nv_bfloat16 g_ch[MROWS*DMODEL],  g_cl[MROWS*DMODEL];
__device__ __nv_bfloat16 g_wh[DMODEL*QKVN],   g_wl[DMODEL*QKVN];   // packed W [K,N]
__device__ __nv_bfloat16 g_woh[DMODEL*DMODEL], g_wol[DMODEL*DMODEL];
__device__ float g_bqkv[QKVN];

// ---------------------------------------------------------------------------
// PTX helpers
// ---------------------------------------------------------------------------
__device__ __forceinline__ uint32_t smem_u32(const void* p) {
    return (uint32_t)__cvta_generic_to_shared(p);
}
__device__ __forceinline__ void ldx4(uint32_t r[4], uint32_t addr) {
    asm volatile("ldmatrix.sync.aligned.m8n8.x4.shared.b16 {%0,%1,%2,%3}, [%4];"
                 : "=r"(r[0]), "=r"(r[1]), "=r"(r[2]), "=r"(r[3]) : "r"(addr));
}
__device__ __forceinline__ void ldx4t(uint32_t r[4], uint32_t addr) {
    asm volatile("ldmatrix.sync.aligned.m8n8.x4.trans.shared.b16 {%0,%1,%2,%3}, [%4];"
                 : "=r"(r[0]), "=r"(r[1]), "=r"(r[2]), "=r"(r[3]) : "r"(addr));
}
__device__ __forceinline__ void mma16816(float c[4], const uint32_t a[4], const uint32_t b[2]) {
    asm volatile("mma.sync.aligned.m16n8k16.row.col.f32.bf16.bf16.f32 "
                 "{%0,%1,%2,%3}, {%4,%5,%6,%7}, {%8,%9}, {%0,%1,%2,%3};"
                 : "+f"(c[0]), "+f"(c[1]), "+f"(c[2]), "+f"(c[3])
                 : "r"(a[0]), "r"(a[1]), "r"(a[2]), "r"(a[3]), "r"(b[0]), "r"(b[1]));
}
__device__ __forceinline__ void cp16s(uint32_t dst, const void* src) {
    asm volatile("cp.async.cg.shared.global [%0], [%1], 16;" :: "r"(dst), "l"(src));
}
#define CP_COMMIT() asm volatile("cp.async.commit_group;")
#define CP_WAIT0()  asm volatile("cp.async.wait_group 0;")
#define CP_WAIT1()  asm volatile("cp.async.wait_group 1;")
__device__ __forceinline__ float ex2(float x) {
    float r; asm("ex2.approx.f32 %0, %1;" : "=f"(r) : "f"(x)); return r;
}

// ---------------------------------------------------------------------------
// fp32 -> (bf16 hi, bf16 lo) elementwise split (for x)
// ---------------------------------------------------------------------------
__global__ void split_kernel(const float4* __restrict__ in,
                             __nv_bfloat162* __restrict__ hi,
                             __nv_bfloat162* __restrict__ lo, int n4)
{
    int i = blockIdx.x * blockDim.x + threadIdx.x;
    if (i >= n4) return;
    float4 f = in[i];
    __nv_bfloat16 h0 = __float2bfloat16(f.x), h1 = __float2bfloat16(f.y);
    __nv_bfloat16 h2 = __float2bfloat16(f.z), h3 = __float2bfloat16(f.w);
    hi[2*i]   = __halves2bfloat162(h0, h1);
    hi[2*i+1] = __halves2bfloat162(h2, h3);
    lo[2*i]   = __floats2bfloat162_rn(f.x - __bfloat162float(h0), f.y - __bfloat162float(h1));
    lo[2*i+1] = __floats2bfloat162_rn(f.z - __bfloat162float(h2), f.w - __bfloat162float(h3));
}

// Split W[K,Nsrc] into packed hi/lo at column offset (ld = ldo)
__global__ void wsplit_kernel(const float* __restrict__ W,
                              __nv_bfloat16* __restrict__ oh,
                              __nv_bfloat16* __restrict__ ol,
                              int Nsrc, int coloff, int ldo, int n4)
{
    int i = blockIdx.x * blockDim.x + threadIdx.x;
    if (i >= n4) return;
    int k  = i / (Nsrc >> 2);
    int c4 = (i - k * (Nsrc >> 2)) << 2;
    float4 f = *(const float4*)&W[(size_t)k * Nsrc + c4];
    __nv_bfloat16 h0 = __float2bfloat16(f.x), h1 = __float2bfloat16(f.y);
    __nv_bfloat16 h2 = __float2bfloat16(f.z), h3 = __float2bfloat16(f.w);
    size_t o = (size_t)k * ldo + coloff + c4;
    *(__nv_bfloat162*)&oh[o]     = __halves2bfloat162(h0, h1);
    *(__nv_bfloat162*)&oh[o + 2] = __halves2bfloat162(h2, h3);
    *(__nv_bfloat162*)&ol[o]     =
        __floats2bfloat162_rn(f.x - __bfloat162float(h0), f.y - __bfloat162float(h1));
    *(__nv_bfloat162*)&ol[o + 2] =
        __floats2bfloat162_rn(f.z - __bfloat162float(h2), f.w - __bfloat162float(h3));
}

__global__ void bias_concat(const float* __restrict__ bq, const float* __restrict__ bk,
                            const float* __restrict__ bv, float* __restrict__ o)
{
    int i = blockIdx.x * 256 + threadIdx.x;
    if (i >= QKVN) return;
    o[i] = (i < DMODEL) ? bq[i] : (i < DMODEL + KVDIM) ? bk[i - DMODEL] : bv[i - DMODEL - KVDIM];
}

// ---------------------------------------------------------------------------
// Split-bf16 MMA GEMM: C[M,N] = A[M,K] @ W[K,N] + bias
// C = AhBh + AhBl + AlBh. Block 128x128, BK=32, 8 warps (warp 64x32),
// cp.async double-buffered, dynamic smem.
// ---------------------------------------------------------------------------
#define APITCH 80    // bytes per A row (32 bf16 = 64B + 16B pad)
#define BPITCH 272   // bytes per B row (128 bf16 = 256B + 16B pad)
#define GA_H 0
#define GA_L 10240
#define GB_H 20480
#define GB_L 29184
#define GSTAGE 37888
#define GEMM_SMEM (2*GSTAGE)

__global__ __launch_bounds__(256) void mma_gemm(
    const __nv_bfloat16* __restrict__ Ahg, const __nv_bfloat16* __restrict__ Alg,
    const __nv_bfloat16* __restrict__ Bhg, const __nv_bfloat16* __restrict__ Blg,
    const float* __restrict__ bias,
    __nv_bfloat16* __restrict__ Ch, __nv_bfloat16* __restrict__ Cl,
    float* __restrict__ Cf,
    int N, int K)
{
    extern __shared__ __align__(16) char smem[];
    const uint32_t sb = smem_u32(smem);

    const int tid  = threadIdx.x;
    const int lane = tid & 31;
    const int warp = tid >> 5;
    const int wm = (warp & 1) * 64;
    const int wn = (warp >> 1) * 32;
    const int bm = blockIdx.y * 128;
    const int bn = blockIdx.x * 128;

    // load mapping (per stage): A 128x32, B 32x128, 8-elem chunks
    const int ar = tid >> 1, ach = (tid & 1) * 2;      // 2 chunks/thread via loop j
    const int br = tid >> 4, bch = tid & 15;

    // ldmatrix lane addressing
    const int a_row = lane & 15;
    const int a_col = (lane >> 4) * 8;
    const int b_row = ((lane >> 3) & 1) * 8 + (lane & 7);
    const int b_col = (lane >> 4) * 8;

    float acc[4][4][4];
#pragma unroll
    for (int i = 0; i < 4; i++)
#pragma unroll
        for (int j = 0; j < 4; j++)
#pragma unroll
            for (int v = 0; v < 4; v++) acc[i][j][v] = 0.f;

    const int NITER = K >> 5;

    auto load_stage = [&](int s, int buf) {
        const uint32_t base = sb + buf * GSTAGE;
        const int k0 = s << 5;
#pragma unroll
        for (int j = 0; j < 2; j++) {
            int ch = ach + j;      // 0..3
            uint32_t off = (uint32_t)(ar * APITCH + ch * 16);
            cp16s(base + GA_H + off, Ahg + (size_t)(bm + ar) * K + k0 + ch * 8);
            cp16s(base + GA_L + off, Alg + (size_t)(bm + ar) * K + k0 + ch * 8);
        }
#pragma unroll
        for (int j = 0; j < 2; j++) {
            int r = br + j * 16;
            uint32_t off = (uint32_t)(r * BPITCH + bch * 16);
            cp16s(base + GB_H + off, Bhg + (size_t)(k0 + r) * N + bn + bch * 8);
            cp16s(base + GB_L + off, Blg + (size_t)(k0 + r) * N + bn + bch * 8);
        }
        CP_COMMIT();
    };

    load_stage(0, 0);

#pragma unroll 1
    for (int s = 0; s < NITER; ++s) {
        const int buf = s & 1;
        if (s + 1 < NITER) { load_stage(s + 1, buf ^ 1); CP_WAIT1(); }
        else CP_WAIT0();
        __syncthreads();

        const uint32_t base = sb + buf * GSTAGE;
#pragma unroll
        for (int ks = 0; ks < 2; ks++) {
            uint32_t ah[4][4], al[4][4];
#pragma unroll
            for (int mt = 0; mt < 4; mt++) {
                uint32_t ao = base + GA_H + (wm + mt * 16 + a_row) * APITCH + (ks * 16 + a_col) * 2;
                ldx4(ah[mt], ao);
                ldx4(al[mt], ao + (GA_L - GA_H));
            }
            uint32_t bh[4][2], bl[4][2];
#pragma unroll
            for (int np = 0; np < 2; np++) {
                uint32_t bo = base + GB_H + (ks * 16 + b_row) * BPITCH + (wn + np * 16 + b_col) * 2;
                uint32_t r[4];
                ldx4t(r, bo);
                bh[np*2][0] = r[0]; bh[np*2][1] = r[1];
                bh[np*2+1][0] = r[2]; bh[np*2+1][1] = r[3];
                ldx4t(r, bo + (GB_L - GB_H));
                bl[np*2][0] = r[0]; bl[np*2][1] = r[1];
                bl[np*2+1][0] = r[2]; bl[np*2+1][1] = r[3];
            }
#pragma unroll
            for (int mt = 0; mt < 4; mt++)
#pragma unroll
                for (int nt = 0; nt < 4; nt++) {
                    mma16816(acc[mt][nt], ah[mt], bh[nt]);
                    mma16816(acc[mt][nt], ah[mt], bl[nt]);
                    mma16816(acc[mt][nt], al[mt], bh[nt]);
                }
        }
        __syncthreads();
    }

    // epilogue
    const int er = lane >> 2;
    const int ec = (lane & 3) * 2;
#pragma unroll
    for (int mt = 0; mt < 4; mt++) {
#pragma unroll
        for (int nt = 0; nt < 4; nt++) {
            int row = bm + wm + mt * 16 + er;
            int col = bn + wn + nt * 8 + ec;
            float b0 = bias[col], b1 = bias[col + 1];
            float v00 = acc[mt][nt][0] + b0, v01 = acc[mt][nt][1] + b1;
            float v10 = acc[mt][nt][2] + b0, v11 = acc[mt][nt][3] + b1;
            if (Cf) {
                *(float2*)&Cf[(size_t)row * N + col]       = make_float2(v00, v01);
                *(float2*)&Cf[(size_t)(row + 8) * N + col] = make_float2(v10, v11);
            } else {
                __nv_bfloat16 h00 = __float2bfloat16(v00), h01 = __float2bfloat16(v01);
                __nv_bfloat16 h10 = __float2bfloat16(v10), h11 = __float2bfloat16(v11);
                *(__nv_bfloat162*)&Ch[(size_t)row * N + col] = __halves2bfloat162(h00, h01);
                *(__nv_bfloat162*)&Cl[(size_t)row * N + col] =
                    __floats2bfloat162_rn(v00 - __bfloat162float(h00), v01 - __bfloat162float(h01));
                *(__nv_bfloat162*)&Ch[(size_t)(row + 8) * N + col] = __halves2bfloat162(h10, h11);
                *(__nv_bfloat162*)&Cl[(size_t)(row + 8) * N + col] =
                    __floats2bfloat162_rn(v10 - __bfloat162float(h10), v11 - __bfloat162float(h11));
            }
        }
    }
}

// ---------------------------------------------------------------------------
// Flash attention, GQA-grouped: CTA = one KV group x 32 q-rows x 4 heads
// (M = 128 = 4 heads * 32 rows; all share K/V). Double-buffered K/V stages.
// Grid (SEQ/32, BSZ*NKV) = (32, 32). 256 threads, 8 warps x 16 M-rows.
// ---------------------------------------------------------------------------
#define FQP 72
#define F_KH 0
#define F_KL 18432
#define F_VH 36864
#define F_VL 55296
#define FSTAGE 73728
#define FLASH_SMEM (2*FSTAGE)

__global__ __launch_bounds__(256) void flash_mma_kernel()
{
    extern __shared__ __align__(16) char smem[];
    const uint32_t sb = smem_u32(smem);

    const int tid  = threadIdx.x;
    const int lane = tid & 31;
    const int warp = tid >> 5;

    const int gid = blockIdx.y;          // b * NKV + kvh
    const int b   = gid >> 3;
    const int kvh = gid & 7;
    const int q0  = blockIdx.x * 32;

    const __nv_bfloat16* QKVh = g_qkvh;
    const __nv_bfloat16* QKVl = g_qkvl;

    // ---- stage Q (M-row m: head kvh*4 + (m>>5), q-row q0 + (m&31)) into buf0 K region
#pragma unroll
    for (int l = 0; l < 4; l++) {
        int id = tid + l * 256;          // 0..1023
        int m = id >> 3, ch = id & 7;
        size_t src = (size_t)(b * SEQ + q0 + (m & 31)) * QKVN
                   + (kvh * 4 + (m >> 5)) * HDIM + ch * 8;
        uint32_t dst = sb + (uint32_t)(m * (FQP * 2) + ch * 16);
        cp16s(dst + F_KH, QKVh + src);
        cp16s(dst + F_KL, QKVl + src);
    }
    CP_COMMIT(); CP_WAIT0();
    __syncthreads();

    const int a_row = lane & 15;
    const int a_col = (lane >> 4) * 8;
    uint32_t qh[4][4], ql[4][4];
#pragma unroll
    for (int ks = 0; ks < 4; ks++) {
        uint32_t ao = sb + (warp * 16 + a_row) * (FQP * 2) + (ks * 16 + a_col) * 2;
        ldx4(qh[ks], ao + F_KH);
        ldx4(ql[ks], ao + F_KL);
    }
    __syncthreads();   // everyone done reading Q before buf0 overwritten

    // ---- K/V loader
    const size_t kbase = (size_t)(b * SEQ) * QKVN + DMODEL + kvh * HDIM;
    auto load_kv = [&](int kb, int buf) {
        const uint32_t base = sb + buf * FSTAGE;
#pragma unroll
        for (int l = 0; l < 4; l++) {
            int id = tid + l * 256;
            int r = id >> 3, ch = id & 7;
            size_t go = kbase + (size_t)(kb * 128 + r) * QKVN + ch * 8;
            uint32_t dst = base + (uint32_t)(r * (FQP * 2) + ch * 16);
            cp16s(dst + F_KH, QKVh + go);
            cp16s(dst + F_KL, QKVl + go);
            cp16s(dst + F_VH, QKVh + go + KVDIM);
            cp16s(dst + F_VL, QKVl + go + KVDIM);
        }
        CP_COMMIT();
    };

    load_kv(0, 0);
    load_kv(1, 1);

    float s[16][4];
    float o[8][4];
#pragma unroll
    for (int i = 0; i < 8; i++)
#pragma unroll
        for (int j = 0; j < 4; j++) o[i][j] = 0.f;
    float m0 = -1e30f, m1 = -1e30f, sum0 = 0.f, sum1 = 0.f;

    const int t_row = ((lane >> 3) & 1) * 8 + (lane & 7);
    const int t_col = (lane >> 4) * 8;

#pragma unroll 1
    for (int kb = 0; kb < SEQ / 128; kb++) {
        const int buf = kb & 1;
        const uint32_t base = sb + buf * FSTAGE;
        if (kb + 1 < SEQ / 128) CP_WAIT1(); else CP_WAIT0();
        __syncthreads();

        // ---- S = Q @ K^T ----
#pragma unroll
        for (int i = 0; i < 16; i++)
#pragma unroll
            for (int j = 0; j < 4; j++) s[i][j] = 0.f;

#pragma unroll
        for (int ntp = 0; ntp < 8; ntp++) {
#pragma unroll
            for (int ks = 0; ks < 4; ks++) {
                uint32_t ko = base + (ntp * 16 + a_row) * (FQP * 2) + (ks * 16 + a_col) * 2;
                uint32_t rh[4], rl[4];
                ldx4(rh, ko + F_KH);
                ldx4(rl, ko + F_KL);
                uint32_t b0h[2] = {rh[0], rh[2]}, b1h[2] = {rh[1], rh[3]};
                uint32_t b0l[2] = {rl[0], rl[2]}, b1l[2] = {rl[1], rl[3]};
                mma16816(s[2*ntp],   qh[ks], b0h);
                mma16816(s[2*ntp],   qh[ks], b0l);
                mma16816(s[2*ntp],   ql[ks], b0h);
                mma16816(s[2*ntp+1], qh[ks], b1h);
                mma16816(s[2*ntp+1], qh[ks], b1l);
                mma16816(s[2*ntp+1], ql[ks], b1h);
            }
        }

        // ---- online softmax (base-2 domain) ----
        const float C2 = 0.18033688011112042f;   // log2(e)/sqrt(64)
        float mx0 = -1e30f, mx1 = -1e30f;
#pragma unroll
        for (int i = 0; i < 16; i++) {
            s[i][0] *= C2; s[i][1] *= C2; s[i][2] *= C2; s[i][3] *= C2;
            mx0 = fmaxf(mx0, fmaxf(s[i][0], s[i][1]));
            mx1 = fmaxf(mx1, fmaxf(s[i][2], s[i][3]));
        }
        mx0 = fmaxf(mx0, __shfl_xor_sync(0xffffffffu, mx0, 1));
        mx0 = fmaxf(mx0, __shfl_xor_sync(0xffffffffu, mx0, 2));
        mx1 = fmaxf(mx1, __shfl_xor_sync(0xffffffffu, mx1, 1));
        mx1 = fmaxf(mx1, __shfl_xor_sync(0xffffffffu, mx1, 2));

        float nm0 = fmaxf(m0, mx0), nm1 = fmaxf(m1, mx1);
        float c0 = ex2(m0 - nm0), c1 = ex2(m1 - nm1);
        m0 = nm0; m1 = nm1;

        float rs0 = 0.f, rs1 = 0.f;
#pragma unroll
        for (int i = 0; i < 16; i++) {
            s[i][0] = ex2(s[i][0] - nm0); rs0 += s[i][0];
            s[i][1] = ex2(s[i][1] - nm0); rs0 += s[i][1];
            s[i][2] = ex2(s[i][2] - nm1); rs1 += s[i][2];
            s[i][3] = ex2(s[i][3] - nm1); rs1 += s[i][3];
        }
        rs0 += __shfl_xor_sync(0xffffffffu, rs0, 1);
        rs0 += __shfl_xor_sync(0xffffffffu, rs0, 2);
        rs1 += __shfl_xor_sync(0xffffffffu, rs1, 1);
        rs1 += __shfl_xor_sync(0xffffffffu, rs1, 2);
        sum0 = sum0 * c0 + rs0;
        sum1 = sum1 * c1 + rs1;
#pragma unroll
        for (int nt = 0; nt < 8; nt++) {
            o[nt][0] *= c0; o[nt][1] *= c0;
            o[nt][2] *= c1; o[nt][3] *= c1;
        }

        // ---- ctx += P @ V ----
#pragma unroll
        for (int ks = 0; ks < 8; ks++) {
            float p00 = s[2*ks][0],   p01 = s[2*ks][1],   p10 = s[2*ks][2],   p11 = s[2*ks][3];
            float r00 = s[2*ks+1][0], r01 = s[2*ks+1][1], r10 = s[2*ks+1][2], r11 = s[2*ks+1][3];
            __nv_bfloat16 hp00 = __float2bfloat16(p00), hp01 = __float2bfloat16(p01);
            __nv_bfloat16 hp10 = __float2bfloat16(p10), hp11 = __float2bfloat16(p11);
            __nv_bfloat16 hr00 = __float2bfloat16(r00), hr01 = __float2bfloat16(r01);
            __nv_bfloat16 hr10 = __float2bfloat16(r10), hr11 = __float2bfloat16(r11);
            __nv_bfloat162 t;
            uint32_t ph[4], pl[4];
            t = __halves2bfloat162(hp00, hp01); ph[0] = *(uint32_t*)&t;
            t = __halves2bfloat162(hp10, hp11); ph[1] = *(uint32_t*)&t;
            t = __halves2bfloat162(hr00, hr01); ph[2] = *(uint32_t*)&t;
            t = __halves2bfloat162(hr10, hr11); ph[3] = *(uint32_t*)&t;
            t = __floats2bfloat162_rn(p00 - __bfloat162float(hp00), p01 - __bfloat162float(hp01)); pl[0] = *(uint32_t*)&t;
            t = __floats2bfloat162_rn(p10 - __bfloat162float(hp10), p11 - __bfloat162float(hp11)); pl[1] = *(uint32_t*)&t;
            t = __floats2bfloat162_rn(r00 - __bfloat162float(hr00), r01 - __bfloat162float(hr01)); pl[2] = *(uint32_t*)&t;
            t = __floats2bfloat162_rn(r10 - __bfloat162float(hr10), r11 - __bfloat162float(hr11)); pl[3] = *(uint32_t*)&t;

#pragma unroll
            for (int np = 0; np < 4; np++) {
                uint32_t vo = base + (ks * 16 + t_row) * (FQP * 2) + (np * 16 + t_col) * 2;
                uint32_t vh4[4], vl4[4];
                ldx4t(vh4, vo + F_VH);
                ldx4t(vl4, vo + F_VL);
                uint32_t v0h[2] = {vh4[0], vh4[1]}, v1h[2] = {vh4[2], vh4[3]};
                uint32_t v0l[2] = {vl4[0], vl4[1]}, v1l[2] = {vl4[2], vl4[3]};
                mma16816(o[np*2],   ph, v0h);
                mma16816(o[np*2],   ph, v0l);
                mma16816(o[np*2],   pl, v0h);
                mma16816(o[np*2+1], ph, v1h);
                mma16816(o[np*2+1], ph, v1l);
                mma16816(o[np*2+1], pl, v1h);
            }
        }

        __syncthreads();
        if (kb + 2 < SEQ / 128) load_kv(kb + 2, buf);
    }

    // ---- normalize + write ctx (hi/lo bf16) ----
    float inv0 = 1.f / sum0, inv1 = 1.f / sum1;
    const int head = kvh * 4 + (warp >> 1);
    const int row0 = b * SEQ + q0 + (warp & 1) * 16 + (lane >> 2);
    const int colb = head * HDIM + (lane & 3) * 2;
#pragma unroll
    for (int nt = 0; nt < 8; nt++) {
        int col = colb + nt * 8;
        float v00 = o[nt][0] * inv0, v01 = o[nt][1] * inv0;
        float v10 = o[nt][2] * inv1, v11 = o[nt][3] * inv1;
        __nv_bfloat16 h00 = __float2bfloat16(v00), h01 = __float2bfloat16(v01);
        __nv_bfloat16 h10 = __float2bfloat16(v10), h11 = __float2bfloat16(v11);
        size_t o0 = (size_t)row0 * DMODEL + col;
        size_t o1 = (size_t)(row0 + 8) * DMODEL + col;
        *(__nv_bfloat162*)&g_ch[o0] = __halves2bfloat162(h00, h01);
        *(__nv_bfloat162*)&g_cl[o0] =
            __floats2bfloat162_rn(v00 - __bfloat162float(h00), v01 - __bfloat162float(h01));
        *(__nv_bfloat162*)&g_ch[o1] = __halves2bfloat162(h10, h11);
        *(__nv_bfloat162*)&g_cl[o1] =
            __floats2bfloat162_rn(v10 - __bfloat162float(h10), v11 - __bfloat162float(h11));
    }
}

// ---------------------------------------------------------------------------
extern "C" void kernel_launch(void* const* d_in, const int* in_sizes, int n_in,
                              void* d_out, int out_size)
{
    const float* x  = (const float*)d_in[0];
    const float* Wq = (const float*)d_in[1];
    const float* bq = (const float*)d_in[2];
    const float* Wk = (const float*)d_in[3];
    const float* bk = (const float*)d_in[4];
    const float* Wv = (const float*)d_in[5];
    const float* bv = (const float*)d_in[6];
    const float* Wo = (const float*)d_in[7];
    const float* bo = (const float*)d_in[8];
    float* out = (float*)d_out;

    __nv_bfloat16 *xh, *xl, *qkvh, *qkvl, *ch, *cl, *wh, *wl, *woh, *wol;
    float* bqkv;
    cudaGetSymbolAddress((void**)&xh, g_xh);     cudaGetSymbolAddress((void**)&xl, g_xl);
    cudaGetSymbolAddress((void**)&qkvh, g_qkvh); cudaGetSymbolAddress((void**)&qkvl, g_qkvl);
    cudaGetSymbolAddress((void**)&ch, g_ch);     cudaGetSymbolAddress((void**)&cl, g_cl);
    cudaGetSymbolAddress((void**)&wh, g_wh);     cudaGetSymbolAddress((void**)&wl, g_wl);
    cudaGetSymbolAddress((void**)&woh, g_woh);   cudaGetSymbolAddress((void**)&wol, g_wol);
    cudaGetSymbolAddress((void**)&bqkv, g_bqkv);

    cudaFuncSetAttribute(mma_gemm, cudaFuncAttributeMaxDynamicSharedMemorySize, GEMM_SMEM);
    cudaFuncSetAttribute(flash_mma_kernel, cudaFuncAttributeMaxDynamicSharedMemorySize, FLASH_SMEM);

    // splits
    int nx = MROWS * DMODEL / 4;
    split_kernel<<<(nx + 255) / 256, 256>>>((const float4*)x,
                                            (__nv_bfloat162*)xh, (__nv_bfloat162*)xl, nx);
    int nq = DMODEL * DMODEL / 4, nk = DMODEL * KVDIM / 4;
    wsplit_kernel<<<(nq + 255) / 256, 256>>>(Wq, wh, wl, DMODEL, 0, QKVN, nq);
    wsplit_kernel<<<(nk + 255) / 256, 256>>>(Wk, wh, wl, KVDIM, DMODEL, QKVN, nk);
    wsplit_kernel<<<(nk + 255) / 256, 256>>>(Wv, wh, wl, KVDIM, DMODEL + KVDIM, QKVN, nk);
    wsplit_kernel<<<(nq + 255) / 256, 256>>>(Wo, woh, wol, DMODEL, 0, DMODEL, nq);
    bias_concat<<<(QKVN + 255) / 256, 256>>>(bq, bk, bv, bqkv);

    dim3 blk(256);
    // fused QKV projection
    mma_gemm<<<dim3(QKVN / 128, MROWS / 128), blk, GEMM_SMEM>>>(
        xh, xl, wh, wl, bqkv, qkvh, qkvl, nullptr, QKVN, DMODEL);

    // attention (GQA-grouped, double-buffered)
    flash_mma_kernel<<<dim3(SEQ / 32, BSZ * NKV), blk, FLASH_SMEM>>>();

    // output projection -> fp32 d_out
    mma_gemm<<<dim3(DMODEL / 128, MROWS / 128), blk, GEMM_SMEM>>>(
        ch, cl, woh, wol, bo, nullptr, nullptr, out, DMODEL, DMODEL);
}